// round 14
// baseline (speedup 1.0000x reference)
#include <cuda_runtime.h>
#include <cuda_bf16.h>
#include <math_constants.h>
#include <cstdint>

#define NB 4096
#define ND 256
#define MARGIN 0.3f
#define EPSV 1e-6f

// scratch (allocation-free rule: __device__ globals)
__device__ float g_dist[(size_t)NB * NB];          // 64 MB distance matrix
__device__ __nv_bfloat16 g_Ehi[(size_t)NB * ND];   // bf16 hi part (2 MB)
__device__ __nv_bfloat16 g_Elo[(size_t)NB * ND];   // bf16 residual (2 MB)
__device__ float g_sq[NB];
__device__ float g_pa[NB];
__device__ float g_vd[NB];
__device__ unsigned g_lmask[64 * 128];             // per-label same-label bitmask (32 KB)
__device__ unsigned int g_cnt;

#define CP16(dst, src) asm volatile("cp.async.cg.shared.global [%0], [%1], 16;" :: "r"(dst), "l"(src))
#define CP_COMMIT()    asm volatile("cp.async.commit_group;" ::: "memory")
#define CP_WAIT0()     asm volatile("cp.async.wait_group 0;" ::: "memory")
#define LDSM4(r, a)    asm volatile("ldmatrix.sync.aligned.m8n8.x4.shared.b16 {%0,%1,%2,%3}, [%4];" \
    : "=r"((r)[0]), "=r"((r)[1]), "=r"((r)[2]), "=r"((r)[3]) : "r"(a))

__device__ __forceinline__ uint32_t smem_u32(const void* p) {
    uint32_t a;
    asm("{ .reg .u64 t; cvta.to.shared.u64 t, %1; cvt.u32.u64 %0, t; }" : "=r"(a) : "l"(p));
    return a;
}

__device__ __forceinline__ void mma_bf16(float* c, const uint32_t* a, const uint32_t* b) {
    asm volatile(
        "mma.sync.aligned.m16n8k16.row.col.f32.bf16.bf16.f32 "
        "{%0,%1,%2,%3}, {%4,%5,%6,%7}, {%8,%9}, {%0,%1,%2,%3};"
        : "+f"(c[0]), "+f"(c[1]), "+f"(c[2]), "+f"(c[3])
        : "r"(a[0]), "r"(a[1]), "r"(a[2]), "r"(a[3]), "r"(b[0]), "r"(b[1]));
}

// ---------------- K-1: split E into bf16 hi + bf16 lo ----------------
__global__ void prep_kernel(const float* __restrict__ E) {
    int i = blockIdx.x * 256 + threadIdx.x;   // float4 index, 262144 total
    float4 v = ((const float4*)E)[i];
    __nv_bfloat16 h[4], l[4];
    float x[4] = {v.x, v.y, v.z, v.w};
#pragma unroll
    for (int q = 0; q < 4; q++) {
        h[q] = __float2bfloat16(x[q]);
        l[q] = __float2bfloat16(x[q] - __bfloat162float(h[q]));
    }
    ((uint64_t*)g_Ehi)[i] = *(uint64_t*)h;
    ((uint64_t*)g_Elo)[i] = *(uint64_t*)l;
}

// ---------------- K0: row squared norms (+ counter reset) ----------------
__global__ void sq_kernel(const float* __restrict__ E) {
    if (blockIdx.x == 0 && threadIdx.x == 0) g_cnt = 0;
    int w = threadIdx.x >> 5, lane = threadIdx.x & 31;
    int r = blockIdx.x * 8 + w;
    const float* row = E + (size_t)r * ND;
    float s = 0.f;
#pragma unroll
    for (int k = 0; k < 8; k++) { float v = row[lane + k * 32]; s += v * v; }
#pragma unroll
    for (int o = 16; o > 0; o >>= 1) s += __shfl_xor_sync(0xffffffffu, s, o);
    if (lane == 0) g_sq[r] = s;
}

// ---------------- K0b: per-label same-label bitmasks ----------------
__global__ void lmask_kernel(const int* __restrict__ labels) {
    __shared__ unsigned char sl[NB];
    int tid = threadIdx.x;   // 128
    for (int q = tid; q < NB / 4; q += 128) {
        int4 lb = ((const int4*)labels)[q];
        ((uchar4*)sl)[q] = make_uchar4((unsigned char)lb.x, (unsigned char)lb.y,
                                       (unsigned char)lb.z, (unsigned char)lb.w);
    }
    __syncthreads();
    int L = blockIdx.x;      // 0..63
    unsigned m = 0;
#pragma unroll 8
    for (int b = 0; b < 32; b++)
        m |= ((unsigned)(sl[tid * 32 + b] == L)) << b;
    g_lmask[L * 128 + tid] = m;
}

// ---------------- K1: bf16x3 symmetric dist GEMM (unchanged from best) ----------------
#define ROWB 80u               // bytes per pane row
#define PANE (128u * ROWB)     // 10240 B
#define BUFSZ (4u * PANE)      // 40960 B
#define DYN_SMEM (2 * 40960)   // 81920 B

__global__ __launch_bounds__(256, 2) void gemm_dist_kernel() {
    extern __shared__ __align__(16) char smem[];
    uint32_t sbase = smem_u32(smem);

    // triangular mapping: bid -> (bm, bn), bm <= bn
    int k = blockIdx.x;
    int bm = 0;
    while (k >= 32 - bm) { k -= 32 - bm; bm++; }
    int bn = bm + k;

    int tid = threadIdx.x;
    int warp = tid >> 5, lane = tid & 31;
    int wm = warp & 3, wn = warp >> 2;     // 4 x 2 warps
    int lr = lane >> 2, lt = lane & 3;

    float acc[2][8][4];
#pragma unroll
    for (int mt = 0; mt < 2; mt++)
#pragma unroll
        for (int nt = 0; nt < 8; nt++)
#pragma unroll
            for (int q = 0; q < 4; q++) acc[mt][nt][q] = 0.f;

    const __nv_bfloat16* srcs[4] = {
        g_Ehi + (size_t)(bm * 128) * ND, g_Elo + (size_t)(bm * 128) * ND,
        g_Ehi + (size_t)(bn * 128) * ND, g_Elo + (size_t)(bn * 128) * ND };

#define FILL(ch, b) do {                                                       \
        uint32_t _d0 = sbase + (uint32_t)(b) * BUFSZ;                          \
        int _k0 = (ch) * 32;                                                   \
        _Pragma("unroll")                                                      \
        for (int q = 0; q < 8; q++) {                                          \
            int g = (q << 8) + tid;                                            \
            int p = g >> 9, w = g & 511;                                       \
            int row = w >> 2, quar = w & 3;                                    \
            CP16(_d0 + (uint32_t)p * PANE + (uint32_t)row * ROWB + (uint32_t)quar * 16u, \
                 srcs[p] + (size_t)row * ND + _k0 + quar * 8);                 \
        }                                                                      \
        CP_COMMIT();                                                           \
    } while (0)

    FILL(0, 0);
    uint32_t aAddr = sbase + (uint32_t)((wm * 32 + (lane & 15)) * ROWB) + ((lane >> 4) * 16u);
    uint32_t bAddr = sbase + 2u * PANE
                   + (uint32_t)((wn * 64 + (lane & 7) + ((lane >> 4) << 3)) * ROWB)
                   + (((lane >> 3) & 1) * 16u);

    for (int ch = 0; ch < 8; ch++) {
        int b = ch & 1;
        CP_WAIT0();
        __syncthreads();
        if (ch < 7) FILL(ch + 1, b ^ 1);
        uint32_t bufo = (uint32_t)b * BUFSZ;
#pragma unroll
        for (int ks = 0; ks < 2; ks++) {
            uint32_t ko = (uint32_t)(ks * 32) + bufo;
            uint32_t ah[2][4], al[2][4];
            uint32_t bb[2][2][4];
            uint32_t a0 = aAddr + ko;
            LDSM4(ah[0], a0);
            LDSM4(al[0], a0 + PANE);
            LDSM4(ah[1], a0 + 16u * ROWB);
            LDSM4(al[1], a0 + 16u * ROWB + PANE);
            uint32_t b0 = bAddr + ko;
            LDSM4(bb[0][0], b0);
            LDSM4(bb[0][1], b0 + PANE);
#pragma unroll
            for (int ntp = 0; ntp < 4; ntp++) {
                int cur = ntp & 1;
                if (ntp < 3) {
                    uint32_t bn_ = b0 + (uint32_t)((ntp + 1) * 16) * ROWB;
                    LDSM4(bb[cur ^ 1][0], bn_);
                    LDSM4(bb[cur ^ 1][1], bn_ + PANE);
                }
#pragma unroll
                for (int mt = 0; mt < 2; mt++)
#pragma unroll
                    for (int sub = 0; sub < 2; sub++) {
                        int nt = 2 * ntp + sub;
                        mma_bf16(acc[mt][nt], ah[mt], &bb[cur][0][2 * sub]);
                        mma_bf16(acc[mt][nt], ah[mt], &bb[cur][1][2 * sub]);
                        mma_bf16(acc[mt][nt], al[mt], &bb[cur][0][2 * sub]);
                    }
            }
        }
    }
    __syncthreads();

    // ---- epilogue: distances, direct + mirrored store ----
    float* T = (float*)smem;                 // 128 x 129 transpose buffer (66048 B)
    float* ssq = (float*)(smem + 66304);     // col norms (bn block)
    if (tid < 128) ssq[tid] = g_sq[bn * 128 + tid];
    __syncthreads();

    int gm0 = bm * 128, gn0 = bn * 128;
#pragma unroll
    for (int mt = 0; mt < 2; mt++) {
        int mr0 = wm * 32 + mt * 16 + lr;
        float sq0 = g_sq[gm0 + mr0];
        float sq1 = g_sq[gm0 + mr0 + 8];
#pragma unroll
        for (int nt = 0; nt < 8; nt++) {
            int nc = wn * 64 + nt * 8 + 2 * lt;
            float sn0 = ssq[nc], sn1 = ssq[nc + 1];
            float d00 = sqrtf(fmaxf(sq0 + sn0 - 2.f * acc[mt][nt][0], 0.f));
            float d01 = sqrtf(fmaxf(sq0 + sn1 - 2.f * acc[mt][nt][1], 0.f));
            float d10 = sqrtf(fmaxf(sq1 + sn0 - 2.f * acc[mt][nt][2], 0.f));
            float d11 = sqrtf(fmaxf(sq1 + sn1 - 2.f * acc[mt][nt][3], 0.f));
            *(float2*)(g_dist + (size_t)(gm0 + mr0) * NB + gn0 + nc) = make_float2(d00, d01);
            *(float2*)(g_dist + (size_t)(gm0 + mr0 + 8) * NB + gn0 + nc) = make_float2(d10, d11);
            if (bm != bn) {
                T[(nc)     * 129 + mr0]     = d00;
                T[(nc + 1) * 129 + mr0]     = d01;
                T[(nc)     * 129 + mr0 + 8] = d10;
                T[(nc + 1) * 129 + mr0 + 8] = d11;
            }
        }
    }
    if (bm != bn) {
        __syncthreads();
        int r = tid >> 1, s = (tid & 1) * 64;
        const float* Tr = T + r * 129 + s;
        float* orow = g_dist + (size_t)(gn0 + r) * NB + gm0 + s;
#pragma unroll
        for (int t4 = 0; t4 < 16; t4++)
            *(float4*)(orow + t4 * 4) = make_float4(Tr[t4*4], Tr[t4*4+1], Tr[t4*4+2], Tr[t4*4+3]);
    }
}

// ---------------- K2: batched mining (bitmask + ballot) + fused finalize ----------------
// 1024 blocks x 256 threads; each block mines 4 rows with double-buffered
// cp.async row prefetch. Pass 1 = values only; pass 2 recovers first-indices
// via ballot/ffs (exact equality against the reduced extrema).
#define SROWS 4
#define SBLOCKS (NB / SROWS)   // 1024

__global__ __launch_bounds__(256) void select_kernel(const float* __restrict__ E,
                                                     const int* __restrict__ labels,
                                                     float* __restrict__ out) {
    __shared__ float sdist[2][NB];           // 32 KB row double-buffer
    __shared__ float swv[8], swv2[8];
    __shared__ unsigned swa[8], swb[8], swc[8];
    __shared__ float sbc[2];
    __shared__ int   sbi[2];
    __shared__ int   slast;
    int tid = threadIdx.x;
    int lane = tid & 31, wrp = tid >> 5;
    int row0 = blockIdx.x * SROWS;
    uint32_t sd0 = smem_u32(&sdist[0][0]);

    // prefetch dist row row0 into buffer 0: 1024 granules, 4/thread
#pragma unroll
    for (int w = 0; w < 4; w++) {
        int q = tid + w * 256;
        CP16(sd0 + (uint32_t)q * 16u, g_dist + (size_t)row0 * NB + q * 4);
    }
    CP_COMMIT();

    for (int t = 0; t < SROWS; t++) {
        int i = row0 + t;
        CP_WAIT0();
        __syncthreads();
        if (t + 1 < SROWS) {
            uint32_t dn = sd0 + (uint32_t)(((t + 1) & 1) * NB) * 4u;
#pragma unroll
            for (int w = 0; w < 4; w++) {
                int q = tid + w * 256;
                CP16(dn + (uint32_t)q * 16u, g_dist + (size_t)(i + 1) * NB + q * 4);
            }
            CP_COMMIT();
        }
        const float* sd = sdist[t & 1];
        int myL = __ldg(&labels[i]);
        const unsigned* lm = g_lmask + myL * 128;

        // pass 1: extrema values only
        float maxpos = -CUDART_INF_F, minneg = CUDART_INF_F;
#pragma unroll
        for (int kq = 0; kq < 16; kq++) {
            int j = tid + kq * 256;
            unsigned mw = __ldg(&lm[j >> 5]);     // uniform per warp
            float d = sd[j];
            bool bit = (mw >> lane) & 1u;
            maxpos = fmaxf(maxpos, (bit && j != i) ? d : -CUDART_INF_F);
            minneg = fminf(minneg, bit ? CUDART_INF_F : d);
        }
#pragma unroll
        for (int o = 16; o > 0; o >>= 1) {
            maxpos = fmaxf(maxpos, __shfl_xor_sync(0xffffffffu, maxpos, o));
            minneg = fminf(minneg, __shfl_xor_sync(0xffffffffu, minneg, o));
        }
        if (lane == 0) { swv[wrp] = maxpos; swv2[wrp] = minneg; }
        __syncthreads();
        if (tid == 0) {
            float v = swv[0], v2 = swv2[0];
#pragma unroll
            for (int wq = 1; wq < 8; wq++) { v = fmaxf(v, swv[wq]); v2 = fminf(v2, swv2[wq]); }
            sbc[0] = v; sbc[1] = v2;
        }
        __syncthreads();
        float AP = sbc[0], ANv = sbc[1];
        bool valid = (AP > -CUDART_INF_F) && (ANv < CUDART_INF_F);

        if (valid) {
            // pass 2: first-index recovery (hp: d==AP pos; hn: d==ANv neg; semi window)
            unsigned hp = 0xffffffffu, hn = 0xffffffffu, sm = 0xffffffffu;
            float thr = AP + MARGIN;
#pragma unroll
            for (int kq = 0; kq < 16; kq++) {
                int j = tid + kq * 256;
                unsigned mw = __ldg(&lm[j >> 5]);
                float d = sd[j];
                bool bit = (mw >> lane) & 1u;
                unsigned bp = __ballot_sync(0xffffffffu, bit && j != i && d == AP);
                unsigned bn_ = __ballot_sync(0xffffffffu, !bit && d == ANv);
                unsigned bs = __ballot_sync(0xffffffffu, !bit && d > AP && d < thr);
                unsigned base = (unsigned)(j - lane);
                if (bp) hp = min(hp, base + (unsigned)__ffs(bp) - 1u);
                if (bn_) hn = min(hn, base + (unsigned)__ffs(bn_) - 1u);
                if (bs) sm = min(sm, base + (unsigned)__ffs(bs) - 1u);
            }
            if (lane == 0) { swa[wrp] = hp; swb[wrp] = hn; swc[wrp] = sm; }
            __syncthreads();
            if (tid == 0) {
                unsigned a = 0xffffffffu, b = 0xffffffffu, c = 0xffffffffu;
#pragma unroll
                for (int wq = 0; wq < 8; wq++) {
                    a = min(a, swa[wq]); b = min(b, swb[wq]); c = min(c, swc[wq]);
                }
                sbi[0] = (int)a;                                  // HPI
                sbi[1] = (c != 0xffffffffu) ? (int)c : (int)b;    // NEG
            }
            __syncthreads();
            int HPI = sbi[0], NEG = sbi[1];

            // triplet margin term recomputed from embeddings (+EPS inside the norm)
            float a = E[(size_t)i * ND + tid];
            float p = E[(size_t)HPI * ND + tid];
            float n = E[(size_t)NEG * ND + tid];
            float dp = a - p + EPSV, dn_ = a - n + EPSV;
            float dp2 = dp * dp, dn2 = dn_ * dn_;
#pragma unroll
            for (int o = 16; o > 0; o >>= 1) {
                dp2 += __shfl_xor_sync(0xffffffffu, dp2, o);
                dn2 += __shfl_xor_sync(0xffffffffu, dn2, o);
            }
            if (lane == 0) { swv[wrp] = dp2; swv2[wrp] = dn2; }
            __syncthreads();
        }

        if (tid == 0) {
            if (valid) {
                float s1 = 0.f, s2 = 0.f;
#pragma unroll
                for (int wq = 0; wq < 8; wq++) { s1 += swv[wq]; s2 += swv2[wq]; }
                float dap = sqrtf(s1), dan = sqrtf(s2);
                g_pa[i] = fmaxf(dap - dan + MARGIN, 0.f);
                g_vd[i] = 1.f;
            } else {
                g_pa[i] = 0.f;
                g_vd[i] = 0.f;
            }
        }
        __syncthreads();   // reductions/buffers free before next row
    }

    if (tid == 0) {
        __threadfence();
        unsigned f = atomicAdd(&g_cnt, 1u);
        slast = (f == SBLOCKS - 1) ? 1 : 0;
    }
    __syncthreads();

    // last block to finish performs the (deterministic fixed-order) final reduction
    if (slast) {
        float a = 0.f, b = 0.f;
        for (int j = tid; j < NB; j += 256) { a += __ldcg(&g_pa[j]); b += __ldcg(&g_vd[j]); }
#pragma unroll
        for (int o = 16; o > 0; o >>= 1) {
            a += __shfl_xor_sync(0xffffffffu, a, o);
            b += __shfl_xor_sync(0xffffffffu, b, o);
        }
        if (lane == 0) { swv[wrp] = a; swv2[wrp] = b; }
        __syncthreads();
        if (tid == 0) {
            float s1 = 0.f, s2 = 0.f;
#pragma unroll
            for (int wq = 0; wq < 8; wq++) { s1 += swv[wq]; s2 += swv2[wq]; }
            out[0] = (s2 > 0.f) ? (s1 / fmaxf(s2, 1.f)) : 0.f;
        }
    }
}

extern "C" void kernel_launch(void* const* d_in, const int* in_sizes, int n_in,
                              void* d_out, int out_size) {
    const float* E = (const float*)d_in[0];
    const int* labels = (const int*)d_in[1];
    cudaFuncSetAttribute(gemm_dist_kernel, cudaFuncAttributeMaxDynamicSharedMemorySize, DYN_SMEM);
    cudaFuncSetAttribute(gemm_dist_kernel, cudaFuncAttributePreferredSharedMemoryCarveout, 100);
    prep_kernel<<<1024, 256>>>(E);
    sq_kernel<<<NB / 8, 256>>>(E);
    lmask_kernel<<<64, 128>>>(labels);
    gemm_dist_kernel<<<528, 256, DYN_SMEM>>>();
    select_kernel<<<SBLOCKS, 256>>>(E, labels, (float*)d_out);   // launch #5
}

// round 16
// speedup vs baseline: 1.2733x; 1.2733x over previous
#include <cuda_runtime.h>
#include <cuda_bf16.h>
#include <math_constants.h>
#include <cstdint>

#define NB 4096
#define ND 256
#define MARGIN 0.3f
#define EPSV 1e-6f

// scratch (allocation-free rule: __device__ globals)
__device__ float g_dist[(size_t)NB * NB];          // 64 MB distance matrix
__device__ __nv_bfloat16 g_Ehi[(size_t)NB * ND];   // bf16 hi part (2 MB)
__device__ __nv_bfloat16 g_Elo[(size_t)NB * ND];   // bf16 residual (2 MB)
__device__ float g_sq[NB];
__device__ float g_pa[NB];
__device__ float g_vd[NB];
__device__ unsigned int g_cnt;

#define CP16(dst, src) asm volatile("cp.async.cg.shared.global [%0], [%1], 16;" :: "r"(dst), "l"(src))
#define CP_COMMIT()    asm volatile("cp.async.commit_group;" ::: "memory")
#define CP_WAIT0()     asm volatile("cp.async.wait_group 0;" ::: "memory")
#define LDSM4(r, a)    asm volatile("ldmatrix.sync.aligned.m8n8.x4.shared.b16 {%0,%1,%2,%3}, [%4];" \
    : "=r"((r)[0]), "=r"((r)[1]), "=r"((r)[2]), "=r"((r)[3]) : "r"(a))

__device__ __forceinline__ uint32_t smem_u32(const void* p) {
    uint32_t a;
    asm("{ .reg .u64 t; cvta.to.shared.u64 t, %1; cvt.u32.u64 %0, t; }" : "=r"(a) : "l"(p));
    return a;
}

__device__ __forceinline__ void mma_bf16(float* c, const uint32_t* a, const uint32_t* b) {
    asm volatile(
        "mma.sync.aligned.m16n8k16.row.col.f32.bf16.bf16.f32 "
        "{%0,%1,%2,%3}, {%4,%5,%6,%7}, {%8,%9}, {%0,%1,%2,%3};"
        : "+f"(c[0]), "+f"(c[1]), "+f"(c[2]), "+f"(c[3])
        : "r"(a[0]), "r"(a[1]), "r"(a[2]), "r"(a[3]), "r"(b[0]), "r"(b[1]));
}

// ---------------- K-1: split E into bf16 hi + bf16 lo ----------------
__global__ void prep_kernel(const float* __restrict__ E) {
    int i = blockIdx.x * 256 + threadIdx.x;   // float4 index, 262144 total
    float4 v = ((const float4*)E)[i];
    __nv_bfloat16 h[4], l[4];
    float x[4] = {v.x, v.y, v.z, v.w};
#pragma unroll
    for (int q = 0; q < 4; q++) {
        h[q] = __float2bfloat16(x[q]);
        l[q] = __float2bfloat16(x[q] - __bfloat162float(h[q]));
    }
    ((uint64_t*)g_Ehi)[i] = *(uint64_t*)h;
    ((uint64_t*)g_Elo)[i] = *(uint64_t*)l;
}

// ---------------- K0: row squared norms (+ counter reset) ----------------
__global__ void sq_kernel(const float* __restrict__ E) {
    if (blockIdx.x == 0 && threadIdx.x == 0) g_cnt = 0;
    int w = threadIdx.x >> 5, lane = threadIdx.x & 31;
    int r = blockIdx.x * 8 + w;
    const float* row = E + (size_t)r * ND;
    float s = 0.f;
#pragma unroll
    for (int k = 0; k < 8; k++) { float v = row[lane + k * 32]; s += v * v; }
#pragma unroll
    for (int o = 16; o > 0; o >>= 1) s += __shfl_xor_sync(0xffffffffu, s, o);
    if (lane == 0) g_sq[r] = s;
}

// ---------------- K1: bf16x3 symmetric dist GEMM (unchanged from best) ----------------
#define ROWB 80u               // bytes per pane row
#define PANE (128u * ROWB)     // 10240 B
#define BUFSZ (4u * PANE)      // 40960 B
#define DYN_SMEM (2 * 40960)   // 81920 B

__global__ __launch_bounds__(256, 2) void gemm_dist_kernel() {
    extern __shared__ __align__(16) char smem[];
    uint32_t sbase = smem_u32(smem);

    // triangular mapping: bid -> (bm, bn), bm <= bn
    int k = blockIdx.x;
    int bm = 0;
    while (k >= 32 - bm) { k -= 32 - bm; bm++; }
    int bn = bm + k;

    int tid = threadIdx.x;
    int warp = tid >> 5, lane = tid & 31;
    int wm = warp & 3, wn = warp >> 2;     // 4 x 2 warps
    int lr = lane >> 2, lt = lane & 3;

    float acc[2][8][4];
#pragma unroll
    for (int mt = 0; mt < 2; mt++)
#pragma unroll
        for (int nt = 0; nt < 8; nt++)
#pragma unroll
            for (int q = 0; q < 4; q++) acc[mt][nt][q] = 0.f;

    const __nv_bfloat16* srcs[4] = {
        g_Ehi + (size_t)(bm * 128) * ND, g_Elo + (size_t)(bm * 128) * ND,
        g_Ehi + (size_t)(bn * 128) * ND, g_Elo + (size_t)(bn * 128) * ND };

#define FILL(ch, b) do {                                                       \
        uint32_t _d0 = sbase + (uint32_t)(b) * BUFSZ;                          \
        int _k0 = (ch) * 32;                                                   \
        _Pragma("unroll")                                                      \
        for (int q = 0; q < 8; q++) {                                          \
            int g = (q << 8) + tid;                                            \
            int p = g >> 9, w = g & 511;                                       \
            int row = w >> 2, quar = w & 3;                                    \
            CP16(_d0 + (uint32_t)p * PANE + (uint32_t)row * ROWB + (uint32_t)quar * 16u, \
                 srcs[p] + (size_t)row * ND + _k0 + quar * 8);                 \
        }                                                                      \
        CP_COMMIT();                                                           \
    } while (0)

    FILL(0, 0);
    uint32_t aAddr = sbase + (uint32_t)((wm * 32 + (lane & 15)) * ROWB) + ((lane >> 4) * 16u);
    uint32_t bAddr = sbase + 2u * PANE
                   + (uint32_t)((wn * 64 + (lane & 7) + ((lane >> 4) << 3)) * ROWB)
                   + (((lane >> 3) & 1) * 16u);

    for (int ch = 0; ch < 8; ch++) {
        int b = ch & 1;
        CP_WAIT0();
        __syncthreads();
        if (ch < 7) FILL(ch + 1, b ^ 1);
        uint32_t bufo = (uint32_t)b * BUFSZ;
#pragma unroll
        for (int ks = 0; ks < 2; ks++) {
            uint32_t ko = (uint32_t)(ks * 32) + bufo;
            uint32_t ah[2][4], al[2][4];
            uint32_t bb[2][2][4];
            uint32_t a0 = aAddr + ko;
            LDSM4(ah[0], a0);
            LDSM4(al[0], a0 + PANE);
            LDSM4(ah[1], a0 + 16u * ROWB);
            LDSM4(al[1], a0 + 16u * ROWB + PANE);
            uint32_t b0 = bAddr + ko;
            LDSM4(bb[0][0], b0);
            LDSM4(bb[0][1], b0 + PANE);
#pragma unroll
            for (int ntp = 0; ntp < 4; ntp++) {
                int cur = ntp & 1;
                if (ntp < 3) {
                    uint32_t bn_ = b0 + (uint32_t)((ntp + 1) * 16) * ROWB;
                    LDSM4(bb[cur ^ 1][0], bn_);
                    LDSM4(bb[cur ^ 1][1], bn_ + PANE);
                }
#pragma unroll
                for (int mt = 0; mt < 2; mt++)
#pragma unroll
                    for (int sub = 0; sub < 2; sub++) {
                        int nt = 2 * ntp + sub;
                        mma_bf16(acc[mt][nt], ah[mt], &bb[cur][0][2 * sub]);
                        mma_bf16(acc[mt][nt], ah[mt], &bb[cur][1][2 * sub]);
                        mma_bf16(acc[mt][nt], al[mt], &bb[cur][0][2 * sub]);
                    }
            }
        }
    }
    __syncthreads();

    // ---- epilogue: distances, direct + mirrored store ----
    float* T = (float*)smem;                 // 128 x 129 transpose buffer (66048 B)
    float* ssq = (float*)(smem + 66304);     // col norms (bn block)
    if (tid < 128) ssq[tid] = g_sq[bn * 128 + tid];
    __syncthreads();

    int gm0 = bm * 128, gn0 = bn * 128;
#pragma unroll
    for (int mt = 0; mt < 2; mt++) {
        int mr0 = wm * 32 + mt * 16 + lr;
        float sq0 = g_sq[gm0 + mr0];
        float sq1 = g_sq[gm0 + mr0 + 8];
#pragma unroll
        for (int nt = 0; nt < 8; nt++) {
            int nc = wn * 64 + nt * 8 + 2 * lt;
            float sn0 = ssq[nc], sn1 = ssq[nc + 1];
            float d00 = sqrtf(fmaxf(sq0 + sn0 - 2.f * acc[mt][nt][0], 0.f));
            float d01 = sqrtf(fmaxf(sq0 + sn1 - 2.f * acc[mt][nt][1], 0.f));
            float d10 = sqrtf(fmaxf(sq1 + sn0 - 2.f * acc[mt][nt][2], 0.f));
            float d11 = sqrtf(fmaxf(sq1 + sn1 - 2.f * acc[mt][nt][3], 0.f));
            *(float2*)(g_dist + (size_t)(gm0 + mr0) * NB + gn0 + nc) = make_float2(d00, d01);
            *(float2*)(g_dist + (size_t)(gm0 + mr0 + 8) * NB + gn0 + nc) = make_float2(d10, d11);
            if (bm != bn) {
                T[(nc)     * 129 + mr0]     = d00;
                T[(nc + 1) * 129 + mr0]     = d01;
                T[(nc)     * 129 + mr0 + 8] = d10;
                T[(nc + 1) * 129 + mr0 + 8] = d11;
            }
        }
    }
    if (bm != bn) {
        __syncthreads();
        int r = tid >> 1, s = (tid & 1) * 64;
        const float* Tr = T + r * 129 + s;
        float* orow = g_dist + (size_t)(gn0 + r) * NB + gm0 + s;
#pragma unroll
        for (int t4 = 0; t4 < 16; t4++)
            *(float4*)(orow + t4 * 4) = make_float4(Tr[t4*4], Tr[t4*4+1], Tr[t4*4+2], Tr[t4*4+3]);
    }
}

// ---------------- K2: batched mining + triplet term + fused finalize ----------------
// R13 select (proven 40.6 us) with ONE change: SROWS 8 -> 4 (1024 blocks)
// to lift grid-limited occupancy (37% -> ~65%).
#define SROWS 4
#define SBLOCKS (NB / SROWS)   // 1024

__global__ __launch_bounds__(256) void select_kernel(const float* __restrict__ E,
                                                     const int* __restrict__ labels,
                                                     float* __restrict__ out) {
    __shared__ float sdist[2][NB];           // 32 KB row double-buffer
    __shared__ unsigned char slab[NB];       // 4 KB label cache
    __shared__ float swv[8], swv2[8];
    __shared__ int   swi[8], swi2[8];
    __shared__ float sbc[2];
    __shared__ int   sbi[2];
    __shared__ int   slast;
    int tid = threadIdx.x;
    int lane = tid & 31, wrp = tid >> 5;
    int row0 = blockIdx.x * SROWS;
    uint32_t sd0 = smem_u32(&sdist[0][0]);

    // cache labels (uchar; labels are 0..63): 1024 int4 over 256 threads
#pragma unroll
    for (int w = 0; w < 4; w++) {
        int q = tid + w * 256;
        int4 lb = ((const int4*)labels)[q];
        ((uchar4*)slab)[q] = make_uchar4((unsigned char)lb.x, (unsigned char)lb.y,
                                         (unsigned char)lb.z, (unsigned char)lb.w);
    }

    // prefetch dist row row0 into buffer 0: 1024 granules, 4/thread
#pragma unroll
    for (int w = 0; w < 4; w++) {
        int q = tid + w * 256;
        CP16(sd0 + (uint32_t)q * 16u, g_dist + (size_t)row0 * NB + q * 4);
    }
    CP_COMMIT();

    for (int t = 0; t < SROWS; t++) {
        int i = row0 + t;
        CP_WAIT0();
        __syncthreads();          // row ready + labels ready + prev row's arrays free
        if (t + 1 < SROWS) {
            uint32_t dn = sd0 + (uint32_t)(((t + 1) & 1) * NB) * 4u;
#pragma unroll
            for (int w = 0; w < 4; w++) {
                int q = tid + w * 256;
                CP16(dn + (uint32_t)q * 16u, g_dist + (size_t)(i + 1) * NB + q * 4);
            }
            CP_COMMIT();
        }
        const float* sd = sdist[t & 1];
        int myL = (int)slab[i];

        // pass 1: hardest positive (first argmax), hardest negative (first argmin)
        float apd = -CUDART_INF_F; int api = 0x7fffffff;
        float andv = CUDART_INF_F; int ani = 0x7fffffff;
#pragma unroll 4
        for (int kq = 0; kq < 16; kq++) {
            int j = tid + kq * 256;
            float d = sd[j];
            int l = (int)slab[j];
            if (l == myL) {
                if (j != i && d > apd) { apd = d; api = j; }
            } else {
                if (d < andv) { andv = d; ani = j; }
            }
        }
#pragma unroll
        for (int o = 16; o > 0; o >>= 1) {
            float ov = __shfl_xor_sync(0xffffffffu, apd, o);
            int   oi = __shfl_xor_sync(0xffffffffu, api, o);
            if (ov > apd || (ov == apd && oi < api)) { apd = ov; api = oi; }
            float ov2 = __shfl_xor_sync(0xffffffffu, andv, o);
            int   oi2 = __shfl_xor_sync(0xffffffffu, ani, o);
            if (ov2 < andv || (ov2 == andv && oi2 < ani)) { andv = ov2; ani = oi2; }
        }
        if (lane == 0) { swv[wrp] = apd; swi[wrp] = api; swv2[wrp] = andv; swi2[wrp] = ani; }
        __syncthreads();
        if (tid == 0) {
            float v = swv[0]; int ix = swi[0];
            float v2 = swv2[0]; int ix2 = swi2[0];
#pragma unroll
            for (int wq = 1; wq < 8; wq++) {
                if (swv[wq] > v || (swv[wq] == v && swi[wq] < ix)) { v = swv[wq]; ix = swi[wq]; }
                if (swv2[wq] < v2 || (swv2[wq] == v2 && swi2[wq] < ix2)) { v2 = swv2[wq]; ix2 = swi2[wq]; }
            }
            sbc[0] = v; sbi[0] = ix; sbc[1] = v2; sbi[1] = ix2;
        }
        __syncthreads();
        float AP = sbc[0]; int HPI = sbi[0];
        float ANv = sbc[1]; int HNI = sbi[1];
        bool valid = (AP > -CUDART_INF_F) && (ANv < CUDART_INF_F);

        if (valid) {
            // pass 2 (SMEM): first semi-hard negative (AP < d < AP + MARGIN)
            unsigned semi = 0xffffffffu;
            float hi_thr = AP + MARGIN;
#pragma unroll 4
            for (int kq = 0; kq < 16; kq++) {
                int j = tid + kq * 256;
                if ((int)slab[j] != myL) {
                    float d = sd[j];
                    if (d > AP && d < hi_thr && (unsigned)j < semi) semi = (unsigned)j;
                }
            }
            semi = __reduce_min_sync(0xffffffffu, semi);
            if (lane == 0) swi[wrp] = (int)semi;
            __syncthreads();
            if (tid == 0) {
                unsigned mn = 0xffffffffu;
#pragma unroll
                for (int wq = 0; wq < 8; wq++) mn = min(mn, (unsigned)swi[wq]);
                sbi[0] = (mn != 0xffffffffu) ? (int)mn : HNI;
            }
            __syncthreads();
            int NEG = sbi[0];

            // triplet margin term recomputed from embeddings (+EPS inside the norm)
            float a = E[(size_t)i * ND + tid];
            float p = E[(size_t)HPI * ND + tid];
            float n = E[(size_t)NEG * ND + tid];
            float dp = a - p + EPSV, dn_ = a - n + EPSV;
            float dp2 = dp * dp, dn2 = dn_ * dn_;
#pragma unroll
            for (int o = 16; o > 0; o >>= 1) {
                dp2 += __shfl_xor_sync(0xffffffffu, dp2, o);
                dn2 += __shfl_xor_sync(0xffffffffu, dn2, o);
            }
            if (lane == 0) { swv[wrp] = dp2; swv2[wrp] = dn2; }
            __syncthreads();
        }

        if (tid == 0) {
            if (valid) {
                float s1 = 0.f, s2 = 0.f;
#pragma unroll
                for (int wq = 0; wq < 8; wq++) { s1 += swv[wq]; s2 += swv2[wq]; }
                float dap = sqrtf(s1), dan = sqrtf(s2);
                g_pa[i] = fmaxf(dap - dan + MARGIN, 0.f);
                g_vd[i] = 1.f;
            } else {
                g_pa[i] = 0.f;
                g_vd[i] = 0.f;
            }
        }
        __syncthreads();   // reductions/buffers free before next row
    }

    if (tid == 0) {
        __threadfence();
        unsigned f = atomicAdd(&g_cnt, 1u);
        slast = (f == SBLOCKS - 1) ? 1 : 0;
    }
    __syncthreads();

    // last block to finish performs the (deterministic fixed-order) final reduction
    if (slast) {
        float a = 0.f, b = 0.f;
        for (int j = tid; j < NB; j += 256) { a += __ldcg(&g_pa[j]); b += __ldcg(&g_vd[j]); }
#pragma unroll
        for (int o = 16; o > 0; o >>= 1) {
            a += __shfl_xor_sync(0xffffffffu, a, o);
            b += __shfl_xor_sync(0xffffffffu, b, o);
        }
        if (lane == 0) { swv[wrp] = a; swv2[wrp] = b; }
        __syncthreads();
        if (tid == 0) {
            float s1 = 0.f, s2 = 0.f;
#pragma unroll
            for (int wq = 0; wq < 8; wq++) { s1 += swv[wq]; s2 += swv2[wq]; }
            out[0] = (s2 > 0.f) ? (s1 / fmaxf(s2, 1.f)) : 0.f;
        }
    }
}

extern "C" void kernel_launch(void* const* d_in, const int* in_sizes, int n_in,
                              void* d_out, int out_size) {
    const float* E = (const float*)d_in[0];
    const int* labels = (const int*)d_in[1];
    cudaFuncSetAttribute(gemm_dist_kernel, cudaFuncAttributeMaxDynamicSharedMemorySize, DYN_SMEM);
    cudaFuncSetAttribute(gemm_dist_kernel, cudaFuncAttributePreferredSharedMemoryCarveout, 100);
    prep_kernel<<<1024, 256>>>(E);
    sq_kernel<<<NB / 8, 256>>>(E);
    gemm_dist_kernel<<<528, 256, DYN_SMEM>>>();
    select_kernel<<<SBLOCKS, 256>>>(E, labels, (float*)d_out);   // launch #4 — profiled slot
}